// round 3
// baseline (speedup 1.0000x reference)
#include <cuda_runtime.h>
#include <math.h>

#define N_NODES   50000
#define N_GRAPHS  64
#define IN_DIM    128
#define HID       64
#define H1        8
#define D1        (H1*HID)          /* 512 */
#define E_MAX     800000
#define ET_MAX    (E_MAX + N_NODES) /* edges + self loops */
#define NEG_SLOPE 0.2f

// ---------------- scratch (static device arrays; no allocation) ----------------
__device__ float g_h1 [N_NODES * D1];     // x @ W1
__device__ float g_o1 [N_NODES * D1];     // relu(gat1)
__device__ float g_h2 [N_NODES * HID];    // o1 @ W2
__device__ float g_o2 [N_NODES * HID];    // relu(gat2)
__device__ float g_as1[H1 * N_NODES];     // transposed: [head][node]
__device__ float g_ad1[H1 * N_NODES];
__device__ float g_as2[N_NODES];
__device__ float g_ad2[N_NODES];
__device__ int   g_csr[ET_MAX];           // src ids grouped by dst
__device__ int   g_off[N_NODES + 1];
__device__ int   g_cnt[N_NODES];          // histogram, then scatter cursor
__device__ float g_pool[N_GRAPHS * HID];

// ---------------- CSR build ----------------
__global__ void zero_k(int n) {
    int i = blockIdx.x * blockDim.x + threadIdx.x;
    if (i < n) g_cnt[i] = 0;
    if (i < N_GRAPHS * HID) g_pool[i] = 0.f;
}

__global__ void hist_k(const int* __restrict__ ei, int E) {
    int i = blockIdx.x * blockDim.x + threadIdx.x;
    if (i < E) atomicAdd(&g_cnt[ei[E + i]], 1);   // dst
}

// single-block scan of (cnt[i] + 1) -> exclusive offsets; also seeds cursor
__global__ void scan_k(int n) {
    __shared__ int part[1024];
    int t = threadIdx.x;
    int ch = (n + 1023) / 1024;
    int b = t * ch, e = min(b + ch, n);
    int s = 0;
    for (int i = b; i < e; i++) s += g_cnt[i] + 1;
    part[t] = s;
    __syncthreads();
    for (int off = 1; off < 1024; off <<= 1) {
        int v = (t >= off) ? part[t - off] : 0;
        __syncthreads();
        part[t] += v;
        __syncthreads();
    }
    int base = (t == 0) ? 0 : part[t - 1];
    for (int i = b; i < e; i++) {
        int c = g_cnt[i];
        g_off[i] = base;
        g_cnt[i] = base;          // cursor for scatter
        base += c + 1;            // +1 reserves self-loop slot
    }
    if (t == 1023) g_off[n] = part[1023];
}

__global__ void scatter_k(const int* __restrict__ ei, int E) {
    int i = blockIdx.x * blockDim.x + threadIdx.x;
    if (i >= E) return;
    int s = ei[i], d = ei[E + i];
    int pos = atomicAdd(&g_cnt[d], 1);
    g_csr[pos] = s;
}

__global__ void selfloop_k(int n) {
    int i = blockIdx.x * blockDim.x + threadIdx.x;
    if (i < n) g_csr[g_off[i + 1] - 1] = i;       // reserved last slot
}

// ---------------- fp32 tiled SGEMM: C[M,N] = A[M,K] * B[K,N] ----------------
// BM=128, BK=16, 256 threads. BN/TN templated (128/8 for gemm1, 64/4 for gemm2).
// N,K multiples of 16; M guarded.
template<int BN, int TN>
__global__ __launch_bounds__(256) void sgemm_t(
    const float* __restrict__ A, const float* __restrict__ B, float* __restrict__ C,
    int M, int N, int K)
{
    constexpr int BM = 128, BK = 16, TM = 8;
    constexpr int BQ = BN * BK / 256 / 4;      // float4's per thread for B (2 or 1)
    __shared__ float As[BK][BM + 4];
    __shared__ float Bs[BK][BN + 4];
    int t = threadIdx.x;
    int m0 = blockIdx.x * BM, n0 = blockIdx.y * BN;

    int arow = t >> 1, acol = (t & 1) * 8;     // 2 threads per A row, 8 floats each
    bool av = (m0 + arow) < M;
    const float* Ap = A + (size_t)(m0 + arow) * K + acol;
    int brow = t >> 4, bcol = (t & 15) * (BQ * 4);
    const float* Bp = B + (size_t)brow * N + n0 + bcol;

    int ty = t / (BN / TN), tx = t % (BN / TN);
    float acc[TM][TN] = {};

    for (int k0 = 0; k0 < K; k0 += BK) {
        float4 a0 = av ? *(const float4*)(Ap + k0)     : make_float4(0,0,0,0);
        float4 a1 = av ? *(const float4*)(Ap + k0 + 4) : make_float4(0,0,0,0);
        As[acol + 0][arow] = a0.x; As[acol + 1][arow] = a0.y;
        As[acol + 2][arow] = a0.z; As[acol + 3][arow] = a0.w;
        As[acol + 4][arow] = a1.x; As[acol + 5][arow] = a1.y;
        As[acol + 6][arow] = a1.z; As[acol + 7][arow] = a1.w;
#pragma unroll
        for (int q = 0; q < BQ; q++) {
            float4 bv = *(const float4*)(Bp + (size_t)k0 * N + q * 4);
            *(float4*)&Bs[brow][bcol + q * 4] = bv;
        }
        __syncthreads();
#pragma unroll
        for (int kk = 0; kk < BK; kk++) {
            float ar[TM], br[TN];
#pragma unroll
            for (int i = 0; i < TM; i += 4) *(float4*)&ar[i] = *(const float4*)&As[kk][ty * TM + i];
#pragma unroll
            for (int j = 0; j < TN; j += 4) *(float4*)&br[j] = *(const float4*)&Bs[kk][tx * TN + j];
#pragma unroll
            for (int i = 0; i < TM; i++)
#pragma unroll
                for (int j = 0; j < TN; j++) acc[i][j] += ar[i] * br[j];
        }
        __syncthreads();
    }
#pragma unroll
    for (int i = 0; i < TM; i++) {
        int m = m0 + ty * TM + i;
        if (m < M) {
#pragma unroll
            for (int j = 0; j < TN; j += 4) {
                float4 v = make_float4(acc[i][j], acc[i][j+1], acc[i][j+2], acc[i][j+3]);
                *(float4*)(C + (size_t)m * N + n0 + tx * TN + j) = v;
            }
        }
    }
}

// ---------------- per-node attention coefficients (transposed output) ----------------
// one warp per (node, head); 8 warps per block; writes os/od as [head][node]
template<int H, int C>
__global__ void alphas_k(const float* __restrict__ h, const float* __restrict__ a_s,
                         const float* __restrict__ a_d, float* __restrict__ os,
                         float* __restrict__ od, int N)
{
    int warp = threadIdx.x >> 5, lane = threadIdx.x & 31;
    constexpr int NPB = 8 / H;
    int node = blockIdx.x * NPB + warp / H;
    int head = warp % H;
    if (node >= N) return;
    const float* hp  = h + (size_t)node * (H * C) + head * C;
    const float* asp = a_s + head * C;
    const float* adp = a_d + head * C;
    float s1 = 0.f, s2 = 0.f;
#pragma unroll
    for (int c = lane; c < C; c += 32) {
        float v = hp[c];
        s1 += v * asp[c];
        s2 += v * adp[c];
    }
#pragma unroll
    for (int o = 16; o; o >>= 1) {
        s1 += __shfl_down_sync(0xffffffffu, s1, o);
        s2 += __shfl_down_sync(0xffffffffu, s2, o);
    }
    if (lane == 0) { os[head * N + node] = s1; od[head * N + node] = s2; }
}

// ---------------- GAT layer: head-phased single-pass aggregation ----------------
// grid = (ceil(N/8), H). All blocks of one head run (approximately) together, so
// the per-head feature slice (N*C*4 = 12.8 MB) stays L2-resident -> gathers hit L2,
// DRAM sees only one compulsory pass per slice.
// One warp per (node, head); lane owns 2 contiguous columns (coalesced 256B/row).
// No max-shift (exp args small at these scales); normalization deferred:
//   out = (sum_i w_i * feat_i) / (sum_i w_i),  w_i = exp(leaky(as[src]+ad[dst]))
template<int H, int C>
__global__ __launch_bounds__(256) void gat_head(
    const float* __restrict__ feat, const float* __restrict__ asT,
    const float* __restrict__ adT, const float* __restrict__ bias,
    float* __restrict__ out, int N)
{
    constexpr int NC = H * C;
    int head = blockIdx.y;
    int node = blockIdx.x * 8 + (threadIdx.x >> 5);
    int lane = threadIdx.x & 31;
    if (node >= N) return;

    int beg = g_off[node], end = g_off[node + 1];
    int deg = end - beg;
    float adl = adT[head * N + node];
    const float* __restrict__ asl = asT + (size_t)head * N;
    const float* fbase = feat + head * C + lane * 2;

    float2 acc = make_float2(0.f, 0.f);
    float wsum = 0.f;

    for (int c0 = 0; c0 < deg; c0 += 32) {
        int k = c0 + lane;
        int s = 0; float w = 0.f;
        if (k < deg) {
            s = g_csr[beg + k];
            float e = asl[s] + adl;
            e = e > 0.f ? e : NEG_SLOPE * e;
            w = __expf(e);
            wsum += w;
        }
        int cnt = min(32, deg - c0);
        for (int i = 0; i < cnt; i++) {
            float wi = __shfl_sync(0xffffffffu, w, i);
            int   si = __shfl_sync(0xffffffffu, s, i);
            float2 f = *(const float2*)(fbase + (size_t)si * NC);
            acc.x += wi * f.x;
            acc.y += wi * f.y;
        }
    }
#pragma unroll
    for (int o = 16; o; o >>= 1) wsum += __shfl_xor_sync(0xffffffffu, wsum, o);

    float inv = 1.f / wsum;
    int col = head * C + lane * 2;
    float v0 = acc.x * inv + bias[col];
    float v1 = acc.y * inv + bias[col + 1];
    out[(size_t)node * NC + col]     = v0 > 0.f ? v0 : 0.f;
    out[(size_t)node * NC + col + 1] = v1 > 0.f ? v1 : 0.f;
}

// ---------------- pooling + FC ----------------
__global__ void pool_k(const int* __restrict__ batch, int N) {
    int i = blockIdx.x * blockDim.x + threadIdx.x;
    if (i >= N * HID) return;
    int n = i >> 6, c = i & 63;
    atomicAdd(&g_pool[batch[n] * HID + c], g_o2[i]);
}

__global__ void fc_k(const float* __restrict__ W, const float* __restrict__ b,
                     float* __restrict__ out)
{
    int t = threadIdx.x;
    if (t >= N_GRAPHS * 10) return;
    int g = t / 10, o = t % 10;
    float s = b[o];
#pragma unroll
    for (int c = 0; c < HID; c++) s += g_pool[g * HID + c] * W[c * 10 + o];
    out[t] = s;
}

// ---------------- host ----------------
extern "C" void kernel_launch(void* const* d_in, const int* in_sizes, int n_in,
                              void* d_out, int out_size)
{
    const float* x      = (const float*)d_in[0];
    const int*   ei     = (const int*)  d_in[1];
    const int*   batch  = (const int*)  d_in[2];
    const float* W1     = (const float*)d_in[3];
    const float* a_src1 = (const float*)d_in[4];
    const float* a_dst1 = (const float*)d_in[5];
    const float* b1     = (const float*)d_in[6];
    const float* W2     = (const float*)d_in[7];
    const float* a_src2 = (const float*)d_in[8];
    const float* a_dst2 = (const float*)d_in[9];
    const float* b2     = (const float*)d_in[10];
    const float* W_fc   = (const float*)d_in[11];
    const float* b_fc   = (const float*)d_in[12];

    int N = in_sizes[0] / IN_DIM;      // 50000
    int E = in_sizes[1] / 2;           // 800000

    float *h1, *o1, *h2, *o2, *as1, *ad1, *as2, *ad2;
    cudaGetSymbolAddress((void**)&h1,  g_h1);
    cudaGetSymbolAddress((void**)&o1,  g_o1);
    cudaGetSymbolAddress((void**)&h2,  g_h2);
    cudaGetSymbolAddress((void**)&o2,  g_o2);
    cudaGetSymbolAddress((void**)&as1, g_as1);
    cudaGetSymbolAddress((void**)&ad1, g_ad1);
    cudaGetSymbolAddress((void**)&as2, g_as2);
    cudaGetSymbolAddress((void**)&ad2, g_ad2);

    // CSR build (by dst) + zero accumulators
    zero_k    <<<(N + 255) / 256, 256>>>(N);
    hist_k    <<<(E + 255) / 256, 256>>>(ei, E);
    scan_k    <<<1, 1024>>>(N);
    scatter_k <<<(E + 255) / 256, 256>>>(ei, E);
    selfloop_k<<<(N + 255) / 256, 256>>>(N);

    // layer 1
    sgemm_t<128, 8><<<dim3((N + 127) / 128, D1 / 128), 256>>>(x, W1, h1, N, D1, IN_DIM);
    alphas_k<H1, HID><<<N, 256>>>(h1, a_src1, a_dst1, as1, ad1, N);
    gat_head<H1, HID><<<dim3((N + 7) / 8, H1), 256>>>(h1, as1, ad1, b1, o1, N);

    // layer 2
    sgemm_t<64, 4><<<dim3((N + 127) / 128, 1), 256>>>(o1, W2, h2, N, HID, D1);
    alphas_k<1, HID><<<(N + 7) / 8, 256>>>(h2, a_src2, a_dst2, as2, ad2, N);
    gat_head<1, HID><<<dim3((N + 7) / 8, 1), 256>>>(h2, as2, ad2, b2, o2, N);

    // pool + fc
    pool_k<<<(N * HID + 255) / 256, 256>>>(batch, N);
    fc_k<<<1, 640>>>(W_fc, b_fc, (float*)d_out);
}

// round 4
// speedup vs baseline: 1.0234x; 1.0234x over previous
#include <cuda_runtime.h>
#include <math.h>

#define N_NODES   50000
#define N_GRAPHS  64
#define IN_DIM    128
#define HID       64
#define H1        8
#define D1        (H1*HID)          /* 512 */
#define E_MAX     800000
#define ET_MAX    (E_MAX + N_NODES) /* edges + self loops */
#define NEG_SLOPE 0.2f

// ---------------- scratch (static device arrays; no allocation) ----------------
__device__ float g_h1 [N_NODES * D1];     // x @ W1
__device__ float g_o1 [N_NODES * D1];     // relu(gat1)
__device__ float g_h2 [N_NODES * HID];    // o1 @ W2
__device__ float g_as1[N_NODES * H1];     // [node][head]
__device__ float g_ad1[N_NODES * H1];
__device__ float g_as2[N_NODES];
__device__ float g_ad2[N_NODES];
__device__ int   g_csr[ET_MAX];           // src ids grouped by dst
__device__ int   g_off[N_NODES + 1];
__device__ int   g_cnt[N_NODES];          // histogram, then scatter cursor
__device__ float g_pool[N_GRAPHS * HID];

// ---------------- zero all accumulators ----------------
__global__ void zero_k(int N) {
    int i = blockIdx.x * blockDim.x + threadIdx.x;
    if (i < N * H1) { g_as1[i] = 0.f; g_ad1[i] = 0.f; }
    if (i < N)      { g_cnt[i] = 0;   g_as2[i] = 0.f; g_ad2[i] = 0.f; }
    if (i < N_GRAPHS * HID) g_pool[i] = 0.f;
}

__global__ void hist_k(const int* __restrict__ ei, int E) {
    int i = blockIdx.x * blockDim.x + threadIdx.x;
    if (i < E) atomicAdd(&g_cnt[ei[E + i]], 1);   // dst
}

// single-block scan of (cnt[i] + 1) -> exclusive offsets; also seeds cursor
__global__ void scan_k(int n) {
    __shared__ int part[1024];
    int t = threadIdx.x;
    int ch = (n + 1023) / 1024;
    int b = t * ch, e = min(b + ch, n);
    int s = 0;
    for (int i = b; i < e; i++) s += g_cnt[i] + 1;
    part[t] = s;
    __syncthreads();
    for (int off = 1; off < 1024; off <<= 1) {
        int v = (t >= off) ? part[t - off] : 0;
        __syncthreads();
        part[t] += v;
        __syncthreads();
    }
    int base = (t == 0) ? 0 : part[t - 1];
    for (int i = b; i < e; i++) {
        int c = g_cnt[i];
        g_off[i] = base;
        g_cnt[i] = base;          // cursor for scatter
        base += c + 1;            // +1 reserves self-loop slot
    }
    if (t == 1023) g_off[n] = part[1023];
}

// scatter edges + fill reserved self-loop slots (one kernel)
__global__ void scatter_self_k(const int* __restrict__ ei, int E, int N) {
    int i = blockIdx.x * blockDim.x + threadIdx.x;
    if (i < E) {
        int s = ei[i], d = ei[E + i];
        g_csr[atomicAdd(&g_cnt[d], 1)] = s;
    } else {
        int n = i - E;
        if (n < N) g_csr[g_off[n + 1] - 1] = n;
    }
}

// ---------------- fp32 tiled SGEMM + fused attention-alpha epilogue ----------------
// C[M,N] = A[M,K] * B[K,N]; also as_out[m*H+h] = sum_c C[m, h*64+c]*avs[h*64+c]
// (same for ad_out/avd). Each (row, head) is covered by exactly one block
// (head width 64 divides BN), reduced in-warp -> direct store, no atomics.
template<int BN, int TN, int H>
__global__ __launch_bounds__(256) void sgemm_ep(
    const float* __restrict__ A, const float* __restrict__ B, float* __restrict__ C,
    const float* __restrict__ avs, const float* __restrict__ avd,
    float* __restrict__ as_out, float* __restrict__ ad_out,
    int M, int N, int K)
{
    constexpr int BM = 128, BK = 16, TM = 8;
    constexpr int BQ = BN * BK / 256 / 4;      // float4's per thread for B (2 or 1)
    __shared__ float As[BK][BM + 4];
    __shared__ float Bs[BK][BN + 4];
    int t = threadIdx.x;
    int m0 = blockIdx.x * BM, n0 = blockIdx.y * BN;

    int arow = t >> 1, acol = (t & 1) * 8;     // 2 threads per A row, 8 floats each
    bool av = (m0 + arow) < M;
    const float* Ap = A + (size_t)(m0 + arow) * K + acol;
    int brow = t >> 4, bcol = (t & 15) * (BQ * 4);
    const float* Bp = B + (size_t)brow * N + n0 + bcol;

    int ty = t / (BN / TN), tx = t % (BN / TN);
    float acc[TM][TN] = {};

    for (int k0 = 0; k0 < K; k0 += BK) {
        float4 a0 = av ? *(const float4*)(Ap + k0)     : make_float4(0,0,0,0);
        float4 a1 = av ? *(const float4*)(Ap + k0 + 4) : make_float4(0,0,0,0);
        As[acol + 0][arow] = a0.x; As[acol + 1][arow] = a0.y;
        As[acol + 2][arow] = a0.z; As[acol + 3][arow] = a0.w;
        As[acol + 4][arow] = a1.x; As[acol + 5][arow] = a1.y;
        As[acol + 6][arow] = a1.z; As[acol + 7][arow] = a1.w;
#pragma unroll
        for (int q = 0; q < BQ; q++) {
            float4 bv = *(const float4*)(Bp + (size_t)k0 * N + q * 4);
            *(float4*)&Bs[brow][bcol + q * 4] = bv;
        }
        __syncthreads();
#pragma unroll
        for (int kk = 0; kk < BK; kk++) {
            float ar[TM], br[TN];
#pragma unroll
            for (int i = 0; i < TM; i += 4) *(float4*)&ar[i] = *(const float4*)&As[kk][ty * TM + i];
#pragma unroll
            for (int j = 0; j < TN; j += 4) *(float4*)&br[j] = *(const float4*)&Bs[kk][tx * TN + j];
#pragma unroll
            for (int i = 0; i < TM; i++)
#pragma unroll
                for (int j = 0; j < TN; j++) acc[i][j] += ar[i] * br[j];
        }
        __syncthreads();
    }
#pragma unroll
    for (int i = 0; i < TM; i++) {
        int m = m0 + ty * TM + i;
        if (m < M) {
#pragma unroll
            for (int j = 0; j < TN; j += 4) {
                float4 v = make_float4(acc[i][j], acc[i][j+1], acc[i][j+2], acc[i][j+3]);
                *(float4*)(C + (size_t)m * N + n0 + tx * TN + j) = v;
            }
        }
    }
    // ---- fused alpha epilogue ----
    constexpr int W = 64 / TN;                 // threads covering one head's 64 cols
    float ars[TN], ard[TN];
#pragma unroll
    for (int j = 0; j < TN; j++) {
        ars[j] = avs[n0 + tx * TN + j];
        ard[j] = avd[n0 + tx * TN + j];
    }
    float ps[TM], pd[TM];
#pragma unroll
    for (int i = 0; i < TM; i++) {
        float s1 = 0.f, s2 = 0.f;
#pragma unroll
        for (int j = 0; j < TN; j++) { s1 += acc[i][j] * ars[j]; s2 += acc[i][j] * ard[j]; }
        ps[i] = s1; pd[i] = s2;
    }
#pragma unroll
    for (int o = 1; o < W; o <<= 1)
#pragma unroll
        for (int i = 0; i < TM; i++) {
            ps[i] += __shfl_xor_sync(0xffffffffu, ps[i], o);
            pd[i] += __shfl_xor_sync(0xffffffffu, pd[i], o);
        }
    if ((tx % W) == 0) {
        int hd = (n0 + tx * TN) / 64;
#pragma unroll
        for (int i = 0; i < TM; i++) {
            int m = m0 + ty * TM + i;
            if (m < M) { as_out[m * H + hd] = ps[i]; ad_out[m * H + hd] = pd[i]; }
        }
    }
}

// ---------------- GAT layer 1: one warp aggregates ALL 8 heads of one node ----
// lane owns 16 contiguous cols (4 x float4) of the 512-wide row; feature head
// of a lane = lane/4. Weights for 8 edges x 8 heads computed in 2 passes
// (lane -> (edge lane/8 [+4], head lane&7)), broadcast by shuffle.
// No max-shift (|e| small at these scales); normalization deferred.
__global__ __launch_bounds__(256) void gat1_k(
    const float* __restrict__ feat, const float* __restrict__ as_,
    const float* __restrict__ ad_, const float* __restrict__ bias,
    float* __restrict__ out, int N)
{
    int warp = threadIdx.x >> 5, lane = threadIdx.x & 31;
    int node = blockIdx.x * 8 + warp;
    if (node >= N) return;
    int beg = g_off[node], end = g_off[node + 1];
    int deg = end - beg;

    float adv  = (lane < 8) ? ad_[node * 8 + lane] : 0.f;
    float advh = __shfl_sync(0xffffffffu, adv, lane & 7);   // ad for head lane&7
    const int hf = lane >> 2;                                // feature head of this lane

    float4 a0 = {0,0,0,0}, a1 = {0,0,0,0}, a2 = {0,0,0,0}, a3 = {0,0,0,0};
    float wsum = 0.f;

    for (int c0 = 0; c0 < deg; c0 += 8) {
        int cnt = min(8, deg - c0);
        int sl = 0;
        if (lane < cnt) sl = g_csr[beg + c0 + lane];
        // weights: pass0 edges 0..3, pass1 edges 4..7; this lane: edge j, head lane&7
        float w0 = 0.f, w1 = 0.f;
        {
            int h = lane & 7;
            int j = lane >> 3;
            int sj = __shfl_sync(0xffffffffu, sl, j);
            if (j < cnt) {
                float e = as_[sj * 8 + h] + advh;
                e = e > 0.f ? e : NEG_SLOPE * e;
                w0 = __expf(e);
            }
            j += 4;
            sj = __shfl_sync(0xffffffffu, sl, j);
            if (j < cnt) {
                float e = as_[sj * 8 + h] + advh;
                e = e > 0.f ? e : NEG_SLOPE * e;
                w1 = __expf(e);
            }
            wsum += w0 + w1;
        }
        for (int i = 0; i < cnt; i++) {
            int   si = __shfl_sync(0xffffffffu, sl, i);
            float wv = (i < 4) ? w0 : w1;
            float wi = __shfl_sync(0xffffffffu, wv, ((i & 3) << 3) + hf);
            const float4* fp = (const float4*)(feat + (size_t)si * D1 + lane * 16);
            float4 f0 = fp[0], f1 = fp[1], f2 = fp[2], f3 = fp[3];
            a0.x += wi * f0.x; a0.y += wi * f0.y; a0.z += wi * f0.z; a0.w += wi * f0.w;
            a1.x += wi * f1.x; a1.y += wi * f1.y; a1.z += wi * f1.z; a1.w += wi * f1.w;
            a2.x += wi * f2.x; a2.y += wi * f2.y; a2.z += wi * f2.z; a2.w += wi * f2.w;
            a3.x += wi * f3.x; a3.y += wi * f3.y; a3.z += wi * f3.z; a3.w += wi * f3.w;
        }
    }
    // per-head wsum: lanes with equal (lane&7) hold same head -> xor 8,16
    wsum += __shfl_xor_sync(0xffffffffu, wsum, 8);
    wsum += __shfl_xor_sync(0xffffffffu, wsum, 16);
    float inv = 1.f / __shfl_sync(0xffffffffu, wsum, hf);    // lane hf holds head hf

    const float4* bp = (const float4*)(bias + lane * 16);
    float4 b0 = bp[0], b1 = bp[1], b2 = bp[2], b3 = bp[3];
    float4 o0, o1, o2, o3;
    o0.x = fmaxf(a0.x * inv + b0.x, 0.f); o0.y = fmaxf(a0.y * inv + b0.y, 0.f);
    o0.z = fmaxf(a0.z * inv + b0.z, 0.f); o0.w = fmaxf(a0.w * inv + b0.w, 0.f);
    o1.x = fmaxf(a1.x * inv + b1.x, 0.f); o1.y = fmaxf(a1.y * inv + b1.y, 0.f);
    o1.z = fmaxf(a1.z * inv + b1.z, 0.f); o1.w = fmaxf(a1.w * inv + b1.w, 0.f);
    o2.x = fmaxf(a2.x * inv + b2.x, 0.f); o2.y = fmaxf(a2.y * inv + b2.y, 0.f);
    o2.z = fmaxf(a2.z * inv + b2.z, 0.f); o2.w = fmaxf(a2.w * inv + b2.w, 0.f);
    o3.x = fmaxf(a3.x * inv + b3.x, 0.f); o3.y = fmaxf(a3.y * inv + b3.y, 0.f);
    o3.z = fmaxf(a3.z * inv + b3.z, 0.f); o3.w = fmaxf(a3.w * inv + b3.w, 0.f);
    float4* op = (float4*)(out + (size_t)node * D1 + lane * 16);
    op[0] = o0; op[1] = o1; op[2] = o2; op[3] = o3;
}

// ---------------- GAT layer 2 fused with ReLU + global_add_pool ----------------
// one warp per node; lane owns 2 cols; result atomicAdd'ed into g_pool directly.
__global__ __launch_bounds__(256) void gat2_k(
    const float* __restrict__ feat, const float* __restrict__ as_,
    const float* __restrict__ ad_, const float* __restrict__ bias,
    const int* __restrict__ batch, int N)
{
    int warp = threadIdx.x >> 5, lane = threadIdx.x & 31;
    int node = blockIdx.x * 8 + warp;
    if (node >= N) return;
    int beg = g_off[node], end = g_off[node + 1];
    int deg = end - beg;
    float adl = ad_[node];

    float2 acc = make_float2(0.f, 0.f);
    float wsum = 0.f;
    for (int c0 = 0; c0 < deg; c0 += 32) {
        int k = c0 + lane;
        int s = 0; float w = 0.f;
        if (k < deg) {
            s = g_csr[beg + k];
            float e = as_[s] + adl;
            e = e > 0.f ? e : NEG_SLOPE * e;
            w = __expf(e);
            wsum += w;
        }
        int cnt = min(32, deg - c0);
        for (int i = 0; i < cnt; i++) {
            float wi = __shfl_sync(0xffffffffu, w, i);
            int   si = __shfl_sync(0xffffffffu, s, i);
            float2 f = *(const float2*)(feat + (size_t)si * HID + lane * 2);
            acc.x += wi * f.x;
            acc.y += wi * f.y;
        }
    }
#pragma unroll
    for (int o = 16; o; o >>= 1) wsum += __shfl_xor_sync(0xffffffffu, wsum, o);
    float inv = 1.f / wsum;
    int col = lane * 2;
    float v0 = fmaxf(acc.x * inv + bias[col],     0.f);
    float v1 = fmaxf(acc.y * inv + bias[col + 1], 0.f);
    int g = batch[node];
    atomicAdd(&g_pool[g * HID + col],     v0);
    atomicAdd(&g_pool[g * HID + col + 1], v1);
}

// ---------------- FC ----------------
__global__ void fc_k(const float* __restrict__ W, const float* __restrict__ b,
                     float* __restrict__ out)
{
    int t = threadIdx.x;
    if (t >= N_GRAPHS * 10) return;
    int g = t / 10, o = t % 10;
    float s = b[o];
#pragma unroll
    for (int c = 0; c < HID; c++) s += g_pool[g * HID + c] * W[c * 10 + o];
    out[t] = s;
}

// ---------------- host ----------------
extern "C" void kernel_launch(void* const* d_in, const int* in_sizes, int n_in,
                              void* d_out, int out_size)
{
    const float* x      = (const float*)d_in[0];
    const int*   ei     = (const int*)  d_in[1];
    const int*   batch  = (const int*)  d_in[2];
    const float* W1     = (const float*)d_in[3];
    const float* a_src1 = (const float*)d_in[4];
    const float* a_dst1 = (const float*)d_in[5];
    const float* b1     = (const float*)d_in[6];
    const float* W2     = (const float*)d_in[7];
    const float* a_src2 = (const float*)d_in[8];
    const float* a_dst2 = (const float*)d_in[9];
    const float* b2     = (const float*)d_in[10];
    const float* W_fc   = (const float*)d_in[11];
    const float* b_fc   = (const float*)d_in[12];

    int N = in_sizes[0] / IN_DIM;      // 50000
    int E = in_sizes[1] / 2;           // 800000

    float *h1, *o1, *h2, *as1, *ad1, *as2, *ad2;
    cudaGetSymbolAddress((void**)&h1,  g_h1);
    cudaGetSymbolAddress((void**)&o1,  g_o1);
    cudaGetSymbolAddress((void**)&h2,  g_h2);
    cudaGetSymbolAddress((void**)&as1, g_as1);
    cudaGetSymbolAddress((void**)&ad1, g_ad1);
    cudaGetSymbolAddress((void**)&as2, g_as2);
    cudaGetSymbolAddress((void**)&ad2, g_ad2);

    // 1..3: zero + degree histogram + offsets
    zero_k<<<(N * H1 + 255) / 256, 256>>>(N);
    hist_k<<<(E + 255) / 256, 256>>>(ei, E);
    scan_k<<<1, 1024>>>(N);
    // 4: GEMM1 + alpha epilogue (profiled launch slot)
    sgemm_ep<128, 8, H1><<<dim3((N + 127) / 128, D1 / 128), 256>>>(
        x, W1, h1, a_src1, a_dst1, as1, ad1, N, D1, IN_DIM);
    // 5: CSR scatter + self-loops
    scatter_self_k<<<(E + N + 255) / 256, 256>>>(ei, E, N);
    // 6: GAT layer 1 (all heads per warp)
    gat1_k<<<(N + 7) / 8, 256>>>(h1, as1, ad1, b1, o1, N);
    // 7: GEMM2 + alpha epilogue
    sgemm_ep<64, 4, 1><<<dim3((N + 127) / 128, 1), 256>>>(
        o1, W2, h2, a_src2, a_dst2, as2, ad2, N, HID, D1);
    // 8: GAT layer 2 fused with ReLU + pool
    gat2_k<<<(N + 7) / 8, 256>>>(h2, as2, ad2, b2, batch, N);
    // 9: FC
    fc_k<<<1, 640>>>(W_fc, b_fc, (float*)d_out);
}

// round 5
// speedup vs baseline: 1.2043x; 1.1768x over previous
#include <cuda_runtime.h>
#include <math.h>

#define N_NODES   50000
#define N_GRAPHS  64
#define IN_DIM    128
#define HID       64
#define H1        8
#define D1        (H1*HID)          /* 512 */
#define E_MAX     800000
#define ET_MAX    (E_MAX + N_NODES) /* edges + self loops */
#define NEG_SLOPE 0.2f

// ---------------- scratch (static device arrays; no allocation) ----------------
__device__ float g_h1 [N_NODES * D1];     // x @ W1
__device__ float g_o1 [N_NODES * D1];     // relu(gat1)
__device__ float g_h2 [N_NODES * HID];    // o1 @ W2
__device__ float g_as1[N_NODES * H1];     // [node][head]
__device__ float g_ad1[N_NODES * H1];
__device__ float g_as2[N_NODES];
__device__ float g_ad2[N_NODES];
__device__ int   g_csr[ET_MAX];           // src ids grouped by dst
__device__ int   g_off[N_NODES + 1];
__device__ int   g_cnt[N_NODES];          // histogram, then scatter cursor
__device__ float g_pool[N_GRAPHS * HID];

// ---------------- zero all accumulators ----------------
__global__ void zero_k(int N) {
    int i = blockIdx.x * blockDim.x + threadIdx.x;
    if (i < N * H1) { g_as1[i] = 0.f; g_ad1[i] = 0.f; }
    if (i < N)      { g_cnt[i] = 0;   g_as2[i] = 0.f; g_ad2[i] = 0.f; }
    if (i < N_GRAPHS * HID) g_pool[i] = 0.f;
}

__global__ void hist_k(const int* __restrict__ ei, int E) {
    int i = blockIdx.x * blockDim.x + threadIdx.x;
    if (i < E) atomicAdd(&g_cnt[ei[E + i]], 1);   // dst
}

// single-block scan of (cnt[i] + 1) -> exclusive offsets; also seeds cursor
__global__ void scan_k(int n) {
    __shared__ int part[1024];
    int t = threadIdx.x;
    int ch = (n + 1023) / 1024;
    int b = t * ch, e = min(b + ch, n);
    int s = 0;
    for (int i = b; i < e; i++) s += g_cnt[i] + 1;
    part[t] = s;
    __syncthreads();
    for (int off = 1; off < 1024; off <<= 1) {
        int v = (t >= off) ? part[t - off] : 0;
        __syncthreads();
        part[t] += v;
        __syncthreads();
    }
    int base = (t == 0) ? 0 : part[t - 1];
    for (int i = b; i < e; i++) {
        int c = g_cnt[i];
        g_off[i] = base;
        g_cnt[i] = base;          // cursor for scatter
        base += c + 1;            // +1 reserves self-loop slot
    }
    if (t == 1023) g_off[n] = part[1023];
}

// scatter edges + fill reserved self-loop slots (one kernel)
__global__ void scatter_self_k(const int* __restrict__ ei, int E, int N) {
    int i = blockIdx.x * blockDim.x + threadIdx.x;
    if (i < E) {
        int s = ei[i], d = ei[E + i];
        g_csr[atomicAdd(&g_cnt[d], 1)] = s;
    } else {
        int n = i - E;
        if (n < N) g_csr[g_off[n + 1] - 1] = n;
    }
}

// ---------------- tf32 tensor-core GEMM + fused alpha epilogue ----------------
__device__ __forceinline__ unsigned f2tf(float f) {
    unsigned u; asm("cvt.rna.tf32.f32 %0, %1;" : "=r"(u) : "f"(f)); return u;
}

// C[M,N] = A[M,K] x B[K,N] via mma.sync m16n8k8 tf32, fp32 accumulate.
// Fused: as_out[m*H + col/64] += sum_c C[m,c]*avs[c]  (atomicAdd partials; pre-zeroed)
// BM=128, BK=32, 256 threads (8 warps, 2x4 warp grid). BN=128 (gemm1) / 64 (gemm2).
// K multiple of 32, N multiple of BN; M guarded.
template<int BN, int H>
__global__ __launch_bounds__(256) void mma_ep(
    const float* __restrict__ A, const float* __restrict__ B, float* __restrict__ C,
    const float* __restrict__ avs, const float* __restrict__ avd,
    float* __restrict__ as_out, float* __restrict__ ad_out,
    int M, int N, int K)
{
    constexpr int BM = 128, BK = 32;
    constexpr int MT = 4, NT = BN / 32;   // warp tile: 64 x (BN/4)
    constexpr int WCOLS = BN / 4;
    constexpr int RS = 9;                 // padded smem row stride (words)
    constexpr int KPT = BK * BN / 256;    // B elements per thread per chunk
    __shared__ unsigned As[4 * BM * RS];
    __shared__ unsigned Bs[4 * BN * RS];

    int t = threadIdx.x, lane = t & 31;
    int wid = t >> 5, wm = wid >> 2, wn = wid & 3;
    int lq = lane >> 2, lp = lane & 3;
    int m0 = blockIdx.x * BM, n0 = blockIdx.y * BN;

    float acc[MT][NT][4];
#pragma unroll
    for (int mt = 0; mt < MT; mt++)
#pragma unroll
        for (int nt = 0; nt < NT; nt++)
#pragma unroll
            for (int v = 0; v < 4; v++) acc[mt][nt][v] = 0.f;

    int ar = t >> 1, acb = (t & 1) * 16;
    bool aok = (m0 + ar) < M;
    const float* Ap = A + (size_t)(m0 + ar) * K + acb;
    int bn = t % BN, bkb = (t / BN) * KPT;

    for (int k0 = 0; k0 < K; k0 += BK) {
        // stage A (tf32-converted), layout As[ks][row][kin], kin 0..7
#pragma unroll
        for (int q = 0; q < 4; q++) {
            int kc = acb + q * 4;                       // multiple of 4
            float4 f = aok ? *(const float4*)(Ap + k0 + q * 4) : make_float4(0,0,0,0);
            unsigned* dst = &As[((kc >> 3) * BM + ar) * RS + (kc & 7)];
            dst[0] = f2tf(f.x); dst[1] = f2tf(f.y); dst[2] = f2tf(f.z); dst[3] = f2tf(f.w);
        }
        // stage B: Bs[ks][n][kin]
#pragma unroll
        for (int i = 0; i < KPT; i++) {
            int kr = bkb + i;
            float v = B[(size_t)(k0 + kr) * N + n0 + bn];
            Bs[((kr >> 3) * BN + bn) * RS + (kr & 7)] = f2tf(v);
        }
        __syncthreads();
#pragma unroll
        for (int ks = 0; ks < 4; ks++) {
            unsigned a0[MT], a1[MT], a2[MT], a3[MT];
#pragma unroll
            for (int mt = 0; mt < MT; mt++) {
                int r = wm * 64 + mt * 16 + lq;
                const unsigned* pl = &As[(ks * BM + r) * RS + lp];
                const unsigned* ph = &As[(ks * BM + r + 8) * RS + lp];
                a0[mt] = pl[0]; a2[mt] = pl[4];
                a1[mt] = ph[0]; a3[mt] = ph[4];
            }
            unsigned b0[NT], b1[NT];
#pragma unroll
            for (int nt = 0; nt < NT; nt++) {
                const unsigned* pb = &Bs[(ks * BN + wn * WCOLS + nt * 8 + lq) * RS + lp];
                b0[nt] = pb[0]; b1[nt] = pb[4];
            }
#pragma unroll
            for (int mt = 0; mt < MT; mt++)
#pragma unroll
                for (int nt = 0; nt < NT; nt++)
                    asm volatile(
                        "mma.sync.aligned.m16n8k8.row.col.f32.tf32.tf32.f32 "
                        "{%0,%1,%2,%3}, {%4,%5,%6,%7}, {%8,%9}, {%0,%1,%2,%3};"
                        : "+f"(acc[mt][nt][0]), "+f"(acc[mt][nt][1]),
                          "+f"(acc[mt][nt][2]), "+f"(acc[mt][nt][3])
                        : "r"(a0[mt]), "r"(a1[mt]), "r"(a2[mt]), "r"(a3[mt]),
                          "r"(b0[nt]), "r"(b1[nt]));
        }
        __syncthreads();
    }

    // store C + fused alpha partial dot products
    float ps[2][MT], pd[2][MT];
#pragma unroll
    for (int mt = 0; mt < MT; mt++) { ps[0][mt]=ps[1][mt]=pd[0][mt]=pd[1][mt]=0.f; }
#pragma unroll
    for (int mt = 0; mt < MT; mt++) {
        int r = m0 + wm * 64 + mt * 16 + lq;
#pragma unroll
        for (int nt = 0; nt < NT; nt++) {
            int c = n0 + wn * WCOLS + nt * 8 + 2 * lp;
            float s0 = avs[c], s1 = avs[c + 1];
            float d0 = avd[c], d1 = avd[c + 1];
            float* a = acc[mt][nt];
            if (r < M)     *(float2*)(C + (size_t)r * N + c)       = make_float2(a[0], a[1]);
            if (r + 8 < M) *(float2*)(C + (size_t)(r + 8) * N + c) = make_float2(a[2], a[3]);
            ps[0][mt] += a[0]*s0 + a[1]*s1;  ps[1][mt] += a[2]*s0 + a[3]*s1;
            pd[0][mt] += a[0]*d0 + a[1]*d1;  pd[1][mt] += a[2]*d0 + a[3]*d1;
        }
    }
#pragma unroll
    for (int o = 1; o <= 2; o <<= 1)
#pragma unroll
        for (int mt = 0; mt < MT; mt++) {
            ps[0][mt] += __shfl_xor_sync(0xffffffffu, ps[0][mt], o);
            ps[1][mt] += __shfl_xor_sync(0xffffffffu, ps[1][mt], o);
            pd[0][mt] += __shfl_xor_sync(0xffffffffu, pd[0][mt], o);
            pd[1][mt] += __shfl_xor_sync(0xffffffffu, pd[1][mt], o);
        }
    if (lp == 0) {
        int head = (n0 + wn * WCOLS) / 64;
#pragma unroll
        for (int mt = 0; mt < MT; mt++) {
            int r = m0 + wm * 64 + mt * 16 + lq;
            if (r < M) {
                atomicAdd(&as_out[r * H + head], ps[0][mt]);
                atomicAdd(&ad_out[r * H + head], pd[0][mt]);
            }
            if (r + 8 < M) {
                atomicAdd(&as_out[(r + 8) * H + head], ps[1][mt]);
                atomicAdd(&ad_out[(r + 8) * H + head], pd[1][mt]);
            }
        }
    }
}

// ---------------- GAT layer 1: one warp aggregates ALL 8 heads of one node ----
// Subtiles of 4 edges, inner loop fully unrolled -> 16 independent LDG.128 in
// flight. Padded subtile slots use weight 0 with a clamped (safe) src row.
// No max-shift (|e| small at these scales); normalization deferred.
__global__ __launch_bounds__(256) void gat1_k(
    const float* __restrict__ feat, const float* __restrict__ as_,
    const float* __restrict__ ad_, const float* __restrict__ bias,
    float* __restrict__ out, int N)
{
    int warp = threadIdx.x >> 5, lane = threadIdx.x & 31;
    int node = blockIdx.x * 8 + warp;
    if (node >= N) return;
    int beg = g_off[node], end = g_off[node + 1];
    int deg = end - beg;

    float advh = ad_[node * 8 + (lane & 7)];   // ad for head lane&7
    const int hf = lane >> 2;                  // feature head of this lane
    const int jj = lane >> 3, hh = lane & 7;   // weight-pass mapping

    float4 a0 = {0,0,0,0}, a1 = {0,0,0,0}, a2 = {0,0,0,0}, a3 = {0,0,0,0};
    float wsum = 0.f;

    for (int c0 = 0; c0 < deg; c0 += 32) {
        int sl = g_csr[beg + min(c0 + lane, deg - 1)];
        int nsub = (min(32, deg - c0) + 3) >> 2;
        for (int sub = 0; sub < nsub; sub++) {
            int e4 = sub * 4;
            // weights for edges e4..e4+3, all 8 heads (lane -> edge jj, head hh)
            int sj = __shfl_sync(0xffffffffu, sl, e4 + jj);
            float w = 0.f;
            if (c0 + e4 + jj < deg) {
                float e = as_[sj * 8 + hh] + advh;
                e = e > 0.f ? e : NEG_SLOPE * e;
                w = __expf(e);
            }
            wsum += w;
#pragma unroll
            for (int i = 0; i < 4; i++) {
                int   si = __shfl_sync(0xffffffffu, sl, e4 + i);
                float wi = __shfl_sync(0xffffffffu, w, i * 8 + hf);
                const float4* fp = (const float4*)(feat + (size_t)si * D1 + lane * 16);
                float4 f0 = fp[0], f1 = fp[1], f2 = fp[2], f3 = fp[3];
                a0.x += wi*f0.x; a0.y += wi*f0.y; a0.z += wi*f0.z; a0.w += wi*f0.w;
                a1.x += wi*f1.x; a1.y += wi*f1.y; a1.z += wi*f1.z; a1.w += wi*f1.w;
                a2.x += wi*f2.x; a2.y += wi*f2.y; a2.z += wi*f2.z; a2.w += wi*f2.w;
                a3.x += wi*f3.x; a3.y += wi*f3.y; a3.z += wi*f3.z; a3.w += wi*f3.w;
            }
        }
    }
    // per-head wsum: combine over jj (bits 3,4 of lane)
    wsum += __shfl_xor_sync(0xffffffffu, wsum, 8);
    wsum += __shfl_xor_sync(0xffffffffu, wsum, 16);
    float inv = 1.f / __shfl_sync(0xffffffffu, wsum, hf);   // lane hf holds head hf

    const float4* bp = (const float4*)(bias + lane * 16);
    float4 b0 = bp[0], b1 = bp[1], b2 = bp[2], b3 = bp[3];
    float4 o0, o1, o2, o3;
    o0.x = fmaxf(a0.x*inv + b0.x, 0.f); o0.y = fmaxf(a0.y*inv + b0.y, 0.f);
    o0.z = fmaxf(a0.z*inv + b0.z, 0.f); o0.w = fmaxf(a0.w*inv + b0.w, 0.f);
    o1.x = fmaxf(a1.x*inv + b1.x, 0.f); o1.y = fmaxf(a1.y*inv + b1.y, 0.f);
    o1.z = fmaxf(a1.z*inv + b1.z, 0.f); o1.w = fmaxf(a1.w*inv + b1.w, 0.f);
    o2.x = fmaxf(a2.x*inv + b2.x, 0.f); o2.y = fmaxf(a2.y*inv + b2.y, 0.f);
    o2.z = fmaxf(a2.z*inv + b2.z, 0.f); o2.w = fmaxf(a2.w*inv + b2.w, 0.f);
    o3.x = fmaxf(a3.x*inv + b3.x, 0.f); o3.y = fmaxf(a3.y*inv + b3.y, 0.f);
    o3.z = fmaxf(a3.z*inv + b3.z, 0.f); o3.w = fmaxf(a3.w*inv + b3.w, 0.f);
    float4* op = (float4*)(out + (size_t)node * D1 + lane * 16);
    op[0] = o0; op[1] = o1; op[2] = o2; op[3] = o3;
}

// ---------------- GAT layer 2 fused with ReLU + global_add_pool ----------------
// one warp per node; lane owns 2 cols; unrolled-by-4 gather; atomicAdd into pool.
__global__ __launch_bounds__(256) void gat2_k(
    const float* __restrict__ feat, const float* __restrict__ as_,
    const float* __restrict__ ad_, const float* __restrict__ bias,
    const int* __restrict__ batch, int N)
{
    int warp = threadIdx.x >> 5, lane = threadIdx.x & 31;
    int node = blockIdx.x * 8 + warp;
    if (node >= N) return;
    int beg = g_off[node], end = g_off[node + 1];
    int deg = end - beg;
    float adl = ad_[node];

    float2 acc = make_float2(0.f, 0.f);
    float wsum = 0.f;
    for (int c0 = 0; c0 < deg; c0 += 32) {
        int k = c0 + lane;
        int s = 0; float w = 0.f;
        if (k < deg) {
            s = g_csr[beg + k];
            float e = as_[s] + adl;
            e = e > 0.f ? e : NEG_SLOPE * e;
            w = __expf(e);
            wsum += w;
        }
        int nit = (min(32, deg - c0) + 3) & ~3;
        for (int i = 0; i < nit; i += 4) {
#pragma unroll
            for (int u = 0; u < 4; u++) {
                float wi = __shfl_sync(0xffffffffu, w, i + u);
                int   si = __shfl_sync(0xffffffffu, s, i + u);
                float2 f = *(const float2*)(feat + (size_t)si * HID + lane * 2);
                acc.x += wi * f.x;
                acc.y += wi * f.y;
            }
        }
    }
#pragma unroll
    for (int o = 16; o; o >>= 1) wsum += __shfl_xor_sync(0xffffffffu, wsum, o);
    float inv = 1.f / wsum;
    int col = lane * 2;
    float v0 = fmaxf(acc.x * inv + bias[col],     0.f);
    float v1 = fmaxf(acc.y * inv + bias[col + 1], 0.f);
    int g = batch[node];
    atomicAdd(&g_pool[g * HID + col],     v0);
    atomicAdd(&g_pool[g * HID + col + 1], v1);
}

// ---------------- FC ----------------
__global__ void fc_k(const float* __restrict__ W, const float* __restrict__ b,
                     float* __restrict__ out)
{
    int t = threadIdx.x;
    if (t >= N_GRAPHS * 10) return;
    int g = t / 10, o = t % 10;
    float s = b[o];
#pragma unroll
    for (int c = 0; c < HID; c++) s += g_pool[g * HID + c] * W[c * 10 + o];
    out[t] = s;
}

// ---------------- host ----------------
extern "C" void kernel_launch(void* const* d_in, const int* in_sizes, int n_in,
                              void* d_out, int out_size)
{
    const float* x      = (const float*)d_in[0];
    const int*   ei     = (const int*)  d_in[1];
    const int*   batch  = (const int*)  d_in[2];
    const float* W1     = (const float*)d_in[3];
    const float* a_src1 = (const float*)d_in[4];
    const float* a_dst1 = (const float*)d_in[5];
    const float* b1     = (const float*)d_in[6];
    const float* W2     = (const float*)d_in[7];
    const float* a_src2 = (const float*)d_in[8];
    const float* a_dst2 = (const float*)d_in[9];
    const float* b2     = (const float*)d_in[10];
    const float* W_fc   = (const float*)d_in[11];
    const float* b_fc   = (const float*)d_in[12];

    int N = in_sizes[0] / IN_DIM;      // 50000
    int E = in_sizes[1] / 2;           // 800000

    float *h1, *o1, *h2, *as1, *ad1, *as2, *ad2;
    cudaGetSymbolAddress((void**)&h1,  g_h1);
    cudaGetSymbolAddress((void**)&o1,  g_o1);
    cudaGetSymbolAddress((void**)&h2,  g_h2);
    cudaGetSymbolAddress((void**)&as1, g_as1);
    cudaGetSymbolAddress((void**)&ad1, g_ad1);
    cudaGetSymbolAddress((void**)&as2, g_as2);
    cudaGetSymbolAddress((void**)&ad2, g_ad2);

    // 1..3: zero + degree histogram + offsets
    zero_k<<<(N * H1 + 255) / 256, 256>>>(N);
    hist_k<<<(E + 255) / 256, 256>>>(ei, E);
    scan_k<<<1, 1024>>>(N);
    // 4: tf32 GEMM1 + alpha epilogue (profiled launch slot)
    mma_ep<128, H1><<<dim3((N + 127) / 128, D1 / 128), 256>>>(
        x, W1, h1, a_src1, a_dst1, as1, ad1, N, D1, IN_DIM);
    // 5: CSR scatter + self-loops
    scatter_self_k<<<(E + N + 255) / 256, 256>>>(ei, E, N);
    // 6: GAT layer 1 (all heads per warp)
    gat1_k<<<(N + 7) / 8, 256>>>(h1, as1, ad1, b1, o1, N);
    // 7: tf32 GEMM2 + alpha epilogue
    mma_ep<64, 1><<<dim3((N + 127) / 128, 1), 256>>>(
        o1, W2, h2, a_src2, a_dst2, as2, ad2, N, HID, D1);
    // 8: GAT layer 2 fused with ReLU + pool
    gat2_k<<<(N + 7) / 8, 256>>>(h2, as2, ad2, b2, batch, N);
    // 9: FC
    fc_k<<<1, 640>>>(W_fc, b_fc, (float*)d_out);
}

// round 7
// speedup vs baseline: 1.5463x; 1.2839x over previous
#include <cuda_runtime.h>
#include <cuda_fp16.h>
#include <math.h>

#define N_NODES   50000
#define N_GRAPHS  64
#define IN_DIM    128
#define HID       64
#define H1        8
#define D1        (H1*HID)          /* 512 */
#define E_MAX     800000
#define ET_MAX    (E_MAX + N_NODES) /* edges + self loops */
#define NEG_SLOPE 0.2f

// ---------------- scratch (static device arrays; no allocation) ----------------
__device__ __half g_h1 [N_NODES * D1];    // x @ W1 (fp16)
__device__ __half g_o1 [N_NODES * D1];    // relu(gat1) (fp16)
__device__ __half g_h2 [N_NODES * HID];   // o1 @ W2 (fp16)
__device__ float g_as1[N_NODES * H1];     // [node][head]
__device__ float g_ad1[N_NODES * H1];
__device__ float g_as2[N_NODES];
__device__ float g_ad2[N_NODES];
__device__ float g_w1 [ET_MAX * H1];      // per-(edge,head) exp weights
__device__ float g_w2 [ET_MAX];
__device__ int   g_csr[ET_MAX];           // src ids grouped by dst
__device__ int   g_dst[ET_MAX];           // dst ids (same order)
__device__ int   g_off[N_NODES + 1];
__device__ int   g_cnt[N_NODES];          // histogram, then scatter cursor
__device__ float g_pool[N_GRAPHS * HID];

struct h2x4 { __half2 a, b, c, d; };      // 16-byte fp16 vector store

// ---------------- zero all accumulators ----------------
__global__ void zero_k(int N) {
    int i = blockIdx.x * blockDim.x + threadIdx.x;
    if (i < N * H1) { g_as1[i] = 0.f; g_ad1[i] = 0.f; }
    if (i < N)      { g_cnt[i] = 0;   g_as2[i] = 0.f; g_ad2[i] = 0.f; }
    if (i < N_GRAPHS * HID) g_pool[i] = 0.f;
}

__global__ void hist_k(const int* __restrict__ ei, int E) {
    int i = blockIdx.x * blockDim.x + threadIdx.x;
    if (i < E) atomicAdd(&g_cnt[ei[E + i]], 1);   // dst
}

// single-block scan of (cnt[i] + 1) -> exclusive offsets; also seeds cursor
__global__ void scan_k(int n) {
    __shared__ int part[1024];
    int t = threadIdx.x;
    int ch = (n + 1023) / 1024;
    int b = t * ch, e = min(b + ch, n);
    int s = 0;
    for (int i = b; i < e; i++) s += g_cnt[i] + 1;
    part[t] = s;
    __syncthreads();
    for (int off = 1; off < 1024; off <<= 1) {
        int v = (t >= off) ? part[t - off] : 0;
        __syncthreads();
        part[t] += v;
        __syncthreads();
    }
    int base = (t == 0) ? 0 : part[t - 1];
    for (int i = b; i < e; i++) {
        int c = g_cnt[i];
        g_off[i] = base;
        g_cnt[i] = base;          // cursor for scatter
        base += c + 1;            // +1 reserves self-loop slot
    }
    if (t == 1023) g_off[n] = part[1023];
}

// scatter edges (+dst ids) + fill reserved self-loop slots
__global__ void scatter_self_k(const int* __restrict__ ei, int E, int N) {
    int i = blockIdx.x * blockDim.x + threadIdx.x;
    if (i < E) {
        int s = ei[i], d = ei[E + i];
        int pos = atomicAdd(&g_cnt[d], 1);
        g_csr[pos] = s;
        g_dst[pos] = d;
    } else {
        int n = i - E;
        if (n < N) {
            int slot = g_off[n + 1] - 1;
            g_csr[slot] = n;
            g_dst[slot] = n;
        }
    }
}

// ---------------- edge-weight precompute ----------------
// thread per (edge, head): w = exp(leaky(as[src][h] + ad[dst][h]))
__global__ void wk1_k(int tot) {
    int i = blockIdx.x * blockDim.x + threadIdx.x;
    if (i >= tot * H1) return;
    int e = i >> 3, h = i & 7;
    int s = g_csr[e], d = g_dst[e];
    float v = g_as1[s * 8 + h] + g_ad1[d * 8 + h];
    v = v > 0.f ? v : NEG_SLOPE * v;
    g_w1[i] = __expf(v);
}

__global__ void wk2_k(int tot) {
    int e = blockIdx.x * blockDim.x + threadIdx.x;
    if (e >= tot) return;
    float v = g_as2[g_csr[e]] + g_ad2[g_dst[e]];
    v = v > 0.f ? v : NEG_SLOPE * v;
    g_w2[e] = __expf(v);
}

// ---------------- tf32 tensor-core GEMM + fused alpha epilogue ----------------
__device__ __forceinline__ unsigned f2tf(float f) {
    unsigned u; asm("cvt.rna.tf32.f32 %0, %1;" : "=r"(u) : "f"(f)); return u;
}
__device__ __forceinline__ float4 ld4(const float* p) { return *(const float4*)p; }
__device__ __forceinline__ float4 ld4(const __half* p) {
    int2 r = *(const int2*)p;
    __half2 h0 = *reinterpret_cast<__half2*>(&r.x);
    __half2 h1 = *reinterpret_cast<__half2*>(&r.y);
    float2 a = __half22float2(h0), b = __half22float2(h1);
    return make_float4(a.x, a.y, b.x, b.y);
}
__device__ __forceinline__ void st2(float* p, float a, float b) {
    *(float2*)p = make_float2(a, b);
}
__device__ __forceinline__ void st2(__half* p, float a, float b) {
    *(__half2*)p = __floats2half2_rn(a, b);
}

// C[M,N] = A[M,K] x B[K,N] via mma.sync m16n8k8 tf32, fp32 accumulate.
// Fused: as_out[m*H + col/64] += sum_c C[m,c]*avs[c]  (atomicAdd partials; pre-zeroed)
// BM=128, BK=32, 256 threads (8 warps, 2x4 warp grid). BN=128 (gemm1) / 64 (gemm2).
template<int BN, int H, typename TA, typename TC>
__global__ __launch_bounds__(256) void mma_ep(
    const TA* __restrict__ A, const float* __restrict__ B, TC* __restrict__ C,
    const float* __restrict__ avs, const float* __restrict__ avd,
    float* __restrict__ as_out, float* __restrict__ ad_out,
    int M, int N, int K)
{
    constexpr int BM = 128, BK = 32;
    constexpr int MT = 4, NT = BN / 32;   // warp tile: 64 x (BN/4)
    constexpr int WCOLS = BN / 4;
    constexpr int RS = 9;                 // padded smem row stride (words)
    constexpr int KPT = BK * BN / 256;    // B elements per thread per chunk
    __shared__ unsigned As[4 * BM * RS];
    __shared__ unsigned Bs[4 * BN * RS];

    int t = threadIdx.x, lane = t & 31;
    int wid = t >> 5, wm = wid >> 2, wn = wid & 3;
    int lq = lane >> 2, lp = lane & 3;
    int m0 = blockIdx.x * BM, n0 = blockIdx.y * BN;

    float acc[MT][NT][4];
#pragma unroll
    for (int mt = 0; mt < MT; mt++)
#pragma unroll
        for (int nt = 0; nt < NT; nt++)
#pragma unroll
            for (int v = 0; v < 4; v++) acc[mt][nt][v] = 0.f;

    int ar = t >> 1, acb = (t & 1) * 16;
    bool aok = (m0 + ar) < M;
    const TA* Ap = A + (size_t)(m0 + ar) * K + acb;
    int bn = t % BN, bkb = (t / BN) * KPT;

    for (int k0 = 0; k0 < K; k0 += BK) {
#pragma unroll
        for (int q = 0; q < 4; q++) {
            int kc = acb + q * 4;                       // multiple of 4
            float4 f = aok ? ld4(Ap + k0 + q * 4) : make_float4(0,0,0,0);
            unsigned* dst = &As[((kc >> 3) * BM + ar) * RS + (kc & 7)];
            dst[0] = f2tf(f.x); dst[1] = f2tf(f.y); dst[2] = f2tf(f.z); dst[3] = f2tf(f.w);
        }
#pragma unroll
        for (int i = 0; i < KPT; i++) {
            int kr = bkb + i;
            float v = B[(size_t)(k0 + kr) * N + n0 + bn];
            Bs[((kr >> 3) * BN + bn) * RS + (kr & 7)] = f2tf(v);
        }
        __syncthreads();
#pragma unroll
        for (int ks = 0; ks < 4; ks++) {
            unsigned a0[MT], a1[MT], a2[MT], a3[MT];
#pragma unroll
            for (int mt = 0; mt < MT; mt++) {
                int r = wm * 64 + mt * 16 + lq;
                const unsigned* pl = &As[(ks * BM + r) * RS + lp];
                const unsigned* ph = &As[(ks * BM + r + 8) * RS + lp];
                a0[mt] = pl[0]; a2[mt] = pl[4];
                a1[mt] = ph[0]; a3[mt] = ph[4];
            }
            unsigned b0[NT], b1[NT];
#pragma unroll
            for (int nt = 0; nt < NT; nt++) {
                const unsigned* pb = &Bs[(ks * BN + wn * WCOLS + nt * 8 + lq) * RS + lp];
                b0[nt] = pb[0]; b1[nt] = pb[4];
            }
#pragma unroll
            for (int mt = 0; mt < MT; mt++)
#pragma unroll
                for (int nt = 0; nt < NT; nt++)
                    asm volatile(
                        "mma.sync.aligned.m16n8k8.row.col.f32.tf32.tf32.f32 "
                        "{%0,%1,%2,%3}, {%4,%5,%6,%7}, {%8,%9}, {%0,%1,%2,%3};"
                        : "+f"(acc[mt][nt][0]), "+f"(acc[mt][nt][1]),
                          "+f"(acc[mt][nt][2]), "+f"(acc[mt][nt][3])
                        : "r"(a0[mt]), "r"(a1[mt]), "r"(a2[mt]), "r"(a3[mt]),
                          "r"(b0[nt]), "r"(b1[nt]));
        }
        __syncthreads();
    }

    // store C + fused alpha partial dot products
    float ps[2][MT], pd[2][MT];
#pragma unroll
    for (int mt = 0; mt < MT; mt++) { ps[0][mt]=ps[1][mt]=pd[0][mt]=pd[1][mt]=0.f; }
#pragma unroll
    for (int mt = 0; mt < MT; mt++) {
        int r = m0 + wm * 64 + mt * 16 + lq;
#pragma unroll
        for (int nt = 0; nt < NT; nt++) {
            int c = n0 + wn * WCOLS + nt * 8 + 2 * lp;
            float s0 = avs[c], s1 = avs[c + 1];
            float d0 = avd[c], d1 = avd[c + 1];
            float* a = acc[mt][nt];
            if (r < M)     st2(C + (size_t)r * N + c,       a[0], a[1]);
            if (r + 8 < M) st2(C + (size_t)(r + 8) * N + c, a[2], a[3]);
            ps[0][mt] += a[0]*s0 + a[1]*s1;  ps[1][mt] += a[2]*s0 + a[3]*s1;
            pd[0][mt] += a[0]*d0 + a[1]*d1;  pd[1][mt] += a[2]*d0 + a[3]*d1;
        }
    }
#pragma unroll
    for (int o = 1; o <= 2; o <<= 1)
#pragma unroll
        for (int mt = 0; mt < MT; mt++) {
            ps[0][mt] += __shfl_xor_sync(0xffffffffu, ps[0][mt], o);
            ps[1][mt] += __shfl_xor_sync(0xffffffffu, ps[1][mt], o);
            pd[0][mt] += __shfl_xor_sync(0xffffffffu, pd[0][mt], o);
            pd[1][mt] += __shfl_xor_sync(0xffffffffu, pd[1][mt], o);
        }
    if (lp == 0) {
        int head = (n0 + wn * WCOLS) / 64;
#pragma unroll
        for (int mt = 0; mt < MT; mt++) {
            int r = m0 + wm * 64 + mt * 16 + lq;
            if (r < M) {
                atomicAdd(&as_out[r * H + head], ps[0][mt]);
                atomicAdd(&ad_out[r * H + head], pd[0][mt]);
            }
            if (r + 8 < M) {
                atomicAdd(&as_out[(r + 8) * H + head], ps[1][mt]);
                atomicAdd(&ad_out[(r + 8) * H + head], pd[1][mt]);
            }
        }
    }
}

// ---------------- GAT layer 1 aggregation ----------------
// 2 warps per node, each owns 256 cols; lane owns 8 fp16 cols (one LDG.128/edge).
// Weights precomputed in g_w1 -> hot loop is pure loads (uniform csr broadcast +
// per-lane w + feature vector). Per-head wsum needs NO reduction: each lane sums
// the w of its own head (identical across the 8 lanes sharing that head).
// Normalization deferred: out = (sum w*f)/(sum w) + bias, then ReLU.
__global__ __launch_bounds__(256) void gat1_k(
    const __half* __restrict__ feat, const float* __restrict__ w1,
    const float* __restrict__ bias, __half* __restrict__ out, int N)
{
    int warp = threadIdx.x >> 5, lane = threadIdx.x & 31;
    int node = blockIdx.x * 4 + (warp >> 1);
    int halfid = warp & 1;
    if (node >= N) return;
    int beg = g_off[node], end = g_off[node + 1];

    int col0 = halfid * 256 + lane * 8;
    int myh  = col0 >> 6;
    const __half* fb = feat + col0;

    float acc[8] = {0,0,0,0,0,0,0,0};
    float wsum = 0.f;

    for (int i = beg; i < end; i += 4) {
#pragma unroll
        for (int u = 0; u < 4; u++) {
            int e = i + u;
            bool ok = e < end;
            e = ok ? e : end - 1;
            int s = g_csr[e];                       // uniform broadcast load
            float w = ok ? w1[e * 8 + myh] : 0.f;   // one 32B sector per edge
            wsum += w;
            uint4 r = *(const uint4*)(fb + (size_t)s * D1);
            float2 f0 = __half22float2(*reinterpret_cast<__half2*>(&r.x));
            float2 f1 = __half22float2(*reinterpret_cast<__half2*>(&r.y));
            float2 f2 = __half22float2(*reinterpret_cast<__half2*>(&r.z));
            float2 f3 = __half22float2(*reinterpret_cast<__half2*>(&r.w));
            acc[0] += w * f0.x; acc[1] += w * f0.y;
            acc[2] += w * f1.x; acc[3] += w * f1.y;
            acc[4] += w * f2.x; acc[5] += w * f2.y;
            acc[6] += w * f3.x; acc[7] += w * f3.y;
        }
    }
    float inv = 1.f / wsum;
    const float4* bp = (const float4*)(bias + col0);
    float4 b0 = bp[0], b1 = bp[1];
    h2x4 pack;
    pack.a = __floats2half2_rn(fmaxf(acc[0]*inv + b0.x, 0.f), fmaxf(acc[1]*inv + b0.y, 0.f));
    pack.b = __floats2half2_rn(fmaxf(acc[2]*inv + b0.z, 0.f), fmaxf(acc[3]*inv + b0.w, 0.f));
    pack.c = __floats2half2_rn(fmaxf(acc[4]*inv + b1.x, 0.f), fmaxf(acc[5]*inv + b1.y, 0.f));
    pack.d = __floats2half2_rn(fmaxf(acc[6]*inv + b1.z, 0.f), fmaxf(acc[7]*inv + b1.w, 0.f));
    *(h2x4*)(out + (size_t)node * D1 + col0) = pack;
}

// ---------------- GAT layer 2 fused with ReLU + global_add_pool ----------------
// one warp per node; lane owns 2 fp16 cols; weights precomputed in g_w2.
__global__ __launch_bounds__(256) void gat2_k(
    const __half* __restrict__ feat, const float* __restrict__ w2,
    const float* __restrict__ bias, const int* __restrict__ batch, int N)
{
    int warp = threadIdx.x >> 5, lane = threadIdx.x & 31;
    int node = blockIdx.x * 8 + warp;
    if (node >= N) return;
    int beg = g_off[node], end = g_off[node + 1];

    float2 acc = make_float2(0.f, 0.f);
    float wsum = 0.f;
    const __half* fb = feat + lane * 2;

    for (int i = beg; i < end; i += 4) {
#pragma unroll
        for (int u = 0; u < 4; u++) {
            int e = i + u;
            bool ok = e < end;
            e = ok ? e : end - 1;
            int s = g_csr[e];
            float w = ok ? w2[e] : 0.f;
            wsum += w;
            __half2 h = *(const __half2*)(fb + (size_t)s * HID);
            float2 f = __half22float2(h);
            acc.x += w * f.x;
            acc.y += w * f.y;
        }
    }
    float inv = 1.f / wsum;
    int col = lane * 2;
    float v0 = fmaxf(acc.x * inv + bias[col],     0.f);
    float v1 = fmaxf(acc.y * inv + bias[col + 1], 0.f);
    int g = batch[node];
    atomicAdd(&g_pool[g * HID + col],     v0);
    atomicAdd(&g_pool[g * HID + col + 1], v1);
}

// ---------------- FC ----------------
__global__ void fc_k(const float* __restrict__ W, const float* __restrict__ b,
                     float* __restrict__ out)
{
    int t = threadIdx.x;
    if (t >= N_GRAPHS * 10) return;
    int g = t / 10, o = t % 10;
    float s = b[o];
#pragma unroll
    for (int c = 0; c < HID; c++) s += g_pool[g * HID + c] * W[c * 10 + o];
    out[t] = s;
}

// ---------------- host ----------------
extern "C" void kernel_launch(void* const* d_in, const int* in_sizes, int n_in,
                              void* d_out, int out_size)
{
    const float* x      = (const float*)d_in[0];
    const int*   ei     = (const int*)  d_in[1];
    const int*   batch  = (const int*)  d_in[2];
    const float* W1     = (const float*)d_in[3];
    const float* a_src1 = (const float*)d_in[4];
    const float* a_dst1 = (const float*)d_in[5];
    const float* b1     = (const float*)d_in[6];
    const float* W2     = (const float*)d_in[7];
    const float* a_src2 = (const float*)d_in[8];
    const float* a_dst2 = (const float*)d_in[9];
    const float* b2     = (const float*)d_in[10];
    const float* W_fc   = (const float*)d_in[11];
    const float* b_fc   = (const float*)d_in[12];

    int N = in_sizes[0] / IN_DIM;      // 50000
    int E = in_sizes[1] / 2;           // 800000
    int ET = E + N;

    __half *h1, *o1, *h2;
    float *as1, *ad1, *as2, *ad2, *w1b, *w2b;
    cudaGetSymbolAddress((void**)&h1,  g_h1);
    cudaGetSymbolAddress((void**)&o1,  g_o1);
    cudaGetSymbolAddress((void**)&h2,  g_h2);
    cudaGetSymbolAddress((void**)&as1, g_as1);
    cudaGetSymbolAddress((void**)&ad1, g_ad1);
    cudaGetSymbolAddress((void**)&as2, g_as2);
    cudaGetSymbolAddress((void**)&ad2, g_ad2);
    cudaGetSymbolAddress((void**)&w1b, g_w1);
    cudaGetSymbolAddress((void**)&w2b, g_w2);

    // 1..3: zero + degree histogram + offsets
    zero_k<<<(N * H1 + 255) / 256, 256>>>(N);
    hist_k<<<(E + 255) / 256, 256>>>(ei, E);
    scan_k<<<1, 1024>>>(N);
    // 4: tf32 GEMM1 + alpha epilogue (profiled slot)
    mma_ep<128, H1><<<dim3((N + 127) / 128, D1 / 128), 256>>>(
        x, W1, h1, a_src1, a_dst1, as1, ad1, N, D1, IN_DIM);
    // 5: CSR scatter (+dst) + self-loops
    scatter_self_k<<<(E + N + 255) / 256, 256>>>(ei, E, N);
    // 6: edge weights layer 1
    wk1_k<<<(ET * H1 + 255) / 256, 256>>>(ET);
    // 7: GAT layer 1 aggregation
    gat1_k<<<(N + 3) / 4, 256>>>(h1, w1b, b1, o1, N);
    // 8: tf32 GEMM2 + alpha epilogue (A fp16)
    mma_ep<64, 1><<<dim3((N + 127) / 128, 1), 256>>>(
        o1, W2, h2, a_src2, a_dst2, as2, ad2, N, HID, D1);
    // 9: edge weights layer 2
    wk2_k<<<(ET + 255) / 256, 256>>>(ET);
    // 10: GAT layer 2 fused with ReLU + pool
    gat2_k<<<(N + 7) / 8, 256>>>(h2, w2b, b2, batch, N);
    // 11: FC
    fc_k<<<1, 640>>>(W_fc, b_fc, (float*)d_out);
}

// round 8
// speedup vs baseline: 1.6781x; 1.0852x over previous
#include <cuda_runtime.h>
#include <cuda_fp16.h>
#include <math.h>

#define N_NODES   50000
#define N_GRAPHS  64
#define IN_DIM    128
#define HID       64
#define H1        8
#define D1        (H1*HID)          /* 512 */
#define E_MAX     800000
#define ET_MAX    (E_MAX + N_NODES) /* edges + self loops */
#define NEG_SLOPE 0.2f

// ---------------- scratch (static device arrays; no allocation) ----------------
__device__ __half g_h1 [N_NODES * D1];    // x @ W1 (fp16)
__device__ __half g_o1 [N_NODES * D1];    // relu(gat1) (fp16)
__device__ __half g_h2 [N_NODES * HID];   // o1 @ W2 (fp16)
__device__ float g_as1[N_NODES * H1];     // [node][head]
__device__ float g_ad1[N_NODES * H1];
__device__ float g_as2[N_NODES];
__device__ float g_ad2[N_NODES];
__device__ float g_w1 [ET_MAX * H1];      // per-(edge,head) exp weights
__device__ float g_w2 [ET_MAX];
__device__ int   g_csr[ET_MAX];           // src ids grouped by dst
__device__ int   g_dst[ET_MAX];           // dst ids (same order)
__device__ int   g_off[N_NODES + 1];
__device__ int   g_cnt[N_NODES];          // histogram, then scatter cursor
__device__ float g_pool[N_GRAPHS * HID];

struct h2x4 { __half2 a, b, c, d; };      // 16-byte fp16 vector store

// ---------------- zero all accumulators ----------------
__global__ void zero_k(int N) {
    int i = blockIdx.x * blockDim.x + threadIdx.x;
    if (i < N * H1) { g_as1[i] = 0.f; g_ad1[i] = 0.f; }
    if (i < N)      { g_cnt[i] = 0;   g_as2[i] = 0.f; g_ad2[i] = 0.f; }
    if (i < N_GRAPHS * HID) g_pool[i] = 0.f;
}

__global__ void hist_k(const int* __restrict__ ei, int E) {
    int i = blockIdx.x * blockDim.x + threadIdx.x;
    if (i < E) atomicAdd(&g_cnt[ei[E + i]], 1);   // dst
}

// single-block scan of (cnt[i] + 1) -> exclusive offsets; also seeds cursor
__global__ void scan_k(int n) {
    __shared__ int part[1024];
    int t = threadIdx.x;
    int ch = (n + 1023) / 1024;
    int b = t * ch, e = min(b + ch, n);
    int s = 0;
    for (int i = b; i < e; i++) s += g_cnt[i] + 1;
    part[t] = s;
    __syncthreads();
    for (int off = 1; off < 1024; off <<= 1) {
        int v = (t >= off) ? part[t - off] : 0;
        __syncthreads();
        part[t] += v;
        __syncthreads();
    }
    int base = (t == 0) ? 0 : part[t - 1];
    for (int i = b; i < e; i++) {
        int c = g_cnt[i];
        g_off[i] = base;
        g_cnt[i] = base;          // cursor for scatter
        base += c + 1;            // +1 reserves self-loop slot
    }
    if (t == 1023) g_off[n] = part[1023];
}

// scatter edges (+dst ids) + fill reserved self-loop slots
__global__ void scatter_self_k(const int* __restrict__ ei, int E, int N) {
    int i = blockIdx.x * blockDim.x + threadIdx.x;
    if (i < E) {
        int s = ei[i], d = ei[E + i];
        int pos = atomicAdd(&g_cnt[d], 1);
        g_csr[pos] = s;
        g_dst[pos] = d;
    } else {
        int n = i - E;
        if (n < N) {
            int slot = g_off[n + 1] - 1;
            g_csr[slot] = n;
            g_dst[slot] = n;
        }
    }
}

// ---------------- edge-weight precompute ----------------
__global__ void wk1_k(int tot) {
    int i = blockIdx.x * blockDim.x + threadIdx.x;
    if (i >= tot * H1) return;
    int e = i >> 3, h = i & 7;
    int s = g_csr[e], d = g_dst[e];
    float v = g_as1[s * 8 + h] + g_ad1[d * 8 + h];
    v = v > 0.f ? v : NEG_SLOPE * v;
    g_w1[i] = __expf(v);
}

__global__ void wk2_k(int tot) {
    int e = blockIdx.x * blockDim.x + threadIdx.x;
    if (e >= tot) return;
    float v = g_as2[g_csr[e]] + g_ad2[g_dst[e]];
    v = v > 0.f ? v : NEG_SLOPE * v;
    g_w2[e] = __expf(v);
}

// ---------------- fp16 tensor-core GEMM + fused alpha epilogue ----------------
__device__ __forceinline__ unsigned pkh2(float a, float b) {
    __half2 h = __floats2half2_rn(a, b);
    return *reinterpret_cast<unsigned*>(&h);
}
// load 16 elements of A row into 2 uint4 (8 half2 words)
__device__ __forceinline__ void ldA16(const float* p, uint4& x, uint4& y) {
    float4 f0 = *(const float4*)p,       f1 = *(const float4*)(p + 4);
    float4 f2 = *(const float4*)(p + 8), f3 = *(const float4*)(p + 12);
    x = make_uint4(pkh2(f0.x, f0.y), pkh2(f0.z, f0.w), pkh2(f1.x, f1.y), pkh2(f1.z, f1.w));
    y = make_uint4(pkh2(f2.x, f2.y), pkh2(f2.z, f2.w), pkh2(f3.x, f3.y), pkh2(f3.z, f3.w));
}
__device__ __forceinline__ void ldA16(const __half* p, uint4& x, uint4& y) {
    x = *(const uint4*)p;
    y = *(const uint4*)(p + 8);
}
__device__ __forceinline__ void st2(float* p, float a, float b) {
    *(float2*)p = make_float2(a, b);
}
__device__ __forceinline__ void st2(__half* p, float a, float b) {
    *(__half2*)p = __floats2half2_rn(a, b);
}

// C[M,N] = A[M,K] x B[K,N] via mma.sync m16n8k16 fp16, fp32 accumulate.
// A/B rounded to fp16 at stage (same 10-bit mantissa as tf32).
// Fused: as_out[m*H + col/64] += sum_c C[m,c]*avs[c] (atomicAdd partials; pre-zeroed)
// BM=128, BK=32, 256 threads (8 warps, 2x4). BN=128 (gemm1) / 64 (gemm2).
template<int BN, int H, typename TA, typename TC>
__global__ __launch_bounds__(256) void mma_ep(
    const TA* __restrict__ A, const float* __restrict__ B, TC* __restrict__ C,
    const float* __restrict__ avs, const float* __restrict__ avd,
    float* __restrict__ as_out, float* __restrict__ ad_out,
    int M, int N, int K)
{
    constexpr int BM = 128, BK = 32;
    constexpr int MT = 4, NT = BN / 32;   // warp tile: 64 x (BN/4)
    constexpr int WCOLS = BN / 4;
    constexpr int RS = 20;                // u32 words per row (16 data + 4 pad)
    constexpr int KE = BK * BN / 256;     // B k-elements per thread (16 or 8)
    __shared__ unsigned As[BM * RS];      // [row][k/2] half2 words
    __shared__ unsigned Bs[BN * RS];      // [n][k/2]   half2 words

    int t = threadIdx.x, lane = t & 31;
    int wid = t >> 5, wm = wid >> 2, wn = wid & 3;
    int lq = lane >> 2, lp = lane & 3;
    int m0 = blockIdx.x * BM, n0 = blockIdx.y * BN;

    float acc[MT][NT][4];
#pragma unroll
    for (int mt = 0; mt < MT; mt++)
#pragma unroll
        for (int nt = 0; nt < NT; nt++)
#pragma unroll
            for (int v = 0; v < 4; v++) acc[mt][nt][v] = 0.f;

    int ar = t >> 1, acb = (t & 1) * 16;
    bool aok = (m0 + ar) < M;
    const TA* Ap = A + (size_t)(m0 + ar) * K + acb;
    int bn = t % BN, bkb = (t / BN) * KE;
    const float* Bp = B + n0 + bn;

    for (int k0 = 0; k0 < K; k0 += BK) {
        // stage A: 16 elems -> 8 half2 words
        uint4 ax = make_uint4(0,0,0,0), ay = make_uint4(0,0,0,0);
        if (aok) ldA16(Ap + k0, ax, ay);
        uint4* adst = (uint4*)&As[ar * RS + (acb >> 1)];
        adst[0] = ax; adst[1] = ay;
        // stage B: KE consecutive k for column bn -> KE/2 half2 words
        unsigned btmp[KE / 2];
#pragma unroll
        for (int j = 0; j < KE / 2; j++) {
            float v0 = Bp[(size_t)(k0 + bkb + 2 * j) * N];
            float v1 = Bp[(size_t)(k0 + bkb + 2 * j + 1) * N];
            btmp[j] = pkh2(v0, v1);
        }
        uint4* bdst = (uint4*)&Bs[bn * RS + (bkb >> 1)];
#pragma unroll
        for (int j = 0; j < KE / 2; j += 4)
            bdst[j >> 2] = make_uint4(btmp[j], btmp[j+1], btmp[j+2], btmp[j+3]);
        __syncthreads();
#pragma unroll
        for (int ks = 0; ks < BK / 16; ks++) {
            unsigned a0[MT], a1[MT], a2[MT], a3[MT];
#pragma unroll
            for (int mt = 0; mt < MT; mt++) {
                int r = wm * 64 + mt * 16 + lq;
                const unsigned* pl = &As[r * RS + ks * 8 + lp];
                const unsigned* ph = &As[(r + 8) * RS + ks * 8 + lp];
                a0[mt] = pl[0]; a2[mt] = pl[4];
                a1[mt] = ph[0]; a3[mt] = ph[4];
            }
            unsigned b0[NT], b1[NT];
#pragma unroll
            for (int nt = 0; nt < NT; nt++) {
                const unsigned* pb = &Bs[(wn * WCOLS + nt * 8 + lq) * RS + ks * 8 + lp];
                b0[nt] = pb[0]; b1[nt] = pb[4];
            }
#pragma unroll
            for (int mt = 0; mt < MT; mt++)
#pragma unroll
                for (int nt = 0; nt < NT; nt++)
                    asm volatile(
                        "mma.sync.aligned.m16n8k16.row.col.f32.f16.f16.f32 "
                        "{%0,%1,%2,%3}, {%4,%5,%6,%7}, {%8,%9}, {%0,%1,%2,%3};"
                        : "+f"(acc[mt][nt][0]), "+f"(acc[mt][nt][1]),
                          "+f"(acc[mt][nt][2]), "+f"(acc[mt][nt][3])
                        : "r"(a0[mt]), "r"(a1[mt]), "r"(a2[mt]), "r"(a3[mt]),
                          "r"(b0[nt]), "r"(b1[nt]));
        }
        __syncthreads();
    }

    // store C + fused alpha partial dot products
    float ps[2][MT], pd[2][MT];
#pragma unroll
    for (int mt = 0; mt < MT; mt++) { ps[0][mt]=ps[1][mt]=pd[0][mt]=pd[1][mt]=0.f; }
#pragma unroll
    for (int mt = 0; mt < MT; mt++) {
        int r = m0 + wm * 64 + mt * 16 + lq;
#pragma unroll
        for (int nt = 0; nt < NT; nt++) {
            int c = n0 + wn * WCOLS + nt * 8 + 2 * lp;
            float s0 = avs[c], s1 = avs[c + 1];
            float d0 = avd[c], d1 = avd[c + 1];
            float* a = acc[mt][nt];
            if (r < M)     st2(C + (size_t)r * N + c,       a[0], a[1]);
            if (r + 8 < M) st2(C + (size_t)(r + 8) * N + c, a[2], a[3]);
            ps[0][mt] += a[0]*s0 + a[1]*s1;  ps[1][mt] += a[2]*s0 + a[3]*s1;
            pd[0][mt] += a[0]*d0 + a[1]*d1;  pd[1][mt] += a[2]*d0 + a[3]*d1;
        }
    }
#pragma unroll
    for (int o = 1; o <= 2; o <<= 1)
#pragma unroll
        for (int mt = 0; mt < MT; mt++) {
            ps[0][mt] += __shfl_xor_sync(0xffffffffu, ps[0][mt], o);
            ps[1][mt] += __shfl_xor_sync(0xffffffffu, ps[1][mt], o);
            pd[0][mt] += __shfl_xor_sync(0xffffffffu, pd[0][mt], o);
            pd[1][mt] += __shfl_xor_sync(0xffffffffu, pd[1][mt], o);
        }
    if (lp == 0) {
        int head = (n0 + wn * WCOLS) / 64;
#pragma unroll
        for (int mt = 0; mt < MT; mt++) {
            int r = m0 + wm * 64 + mt * 16 + lq;
            if (r < M) {
                atomicAdd(&as_out[r * H + head], ps[0][mt]);
                atomicAdd(&ad_out[r * H + head], pd[0][mt]);
            }
            if (r + 8 < M) {
                atomicAdd(&as_out[(r + 8) * H + head], ps[1][mt]);
                atomicAdd(&ad_out[(r + 8) * H + head], pd[1][mt]);
            }
        }
    }
}

// ---------------- GAT layer 1 aggregation ----------------
// 2 warps per node, each owns 256 cols; lane owns 8 fp16 cols (one LDG.128/edge).
// Weights precomputed; (csr,w) for the NEXT 4-edge group prefetched while the
// current group's features are accumulated (breaks the csr->feature chain).
__global__ __launch_bounds__(256) void gat1_k(
    const __half* __restrict__ feat, const float* __restrict__ w1,
    const float* __restrict__ bias, __half* __restrict__ out, int N)
{
    int warp = threadIdx.x >> 5, lane = threadIdx.x & 31;
    int node = blockIdx.x * 4 + (warp >> 1);
    int halfid = warp & 1;
    if (node >= N) return;
    int beg = g_off[node], end = g_off[node + 1];

    int col0 = halfid * 256 + lane * 8;
    int myh  = col0 >> 6;
    const __half* fb = feat + col0;

    float acc[8] = {0,0,0,0,0,0,0,0};
    float wsum = 0.f;

    int cs[4]; float cw[4];
#pragma unroll
    for (int u = 0; u < 4; u++) {
        int e = beg + u; bool ok = e < end; e = ok ? e : end - 1;
        cs[u] = g_csr[e];
        cw[u] = ok ? w1[e * 8 + myh] : 0.f;
    }
    for (int i = beg; i < end; i += 4) {
        int ns[4] = {0,0,0,0}; float nw[4] = {0,0,0,0};
        int nb = i + 4;
        if (nb < end) {
#pragma unroll
            for (int u = 0; u < 4; u++) {
                int e = nb + u; bool ok = e < end; e = ok ? e : end - 1;
                ns[u] = g_csr[e];
                nw[u] = ok ? w1[e * 8 + myh] : 0.f;
            }
        }
#pragma unroll
        for (int u = 0; u < 4; u++) {
            float w = cw[u];
            wsum += w;
            uint4 r = *(const uint4*)(fb + (size_t)cs[u] * D1);
            float2 f0 = __half22float2(*reinterpret_cast<__half2*>(&r.x));
            float2 f1 = __half22float2(*reinterpret_cast<__half2*>(&r.y));
            float2 f2 = __half22float2(*reinterpret_cast<__half2*>(&r.z));
            float2 f3 = __half22float2(*reinterpret_cast<__half2*>(&r.w));
            acc[0] += w * f0.x; acc[1] += w * f0.y;
            acc[2] += w * f1.x; acc[3] += w * f1.y;
            acc[4] += w * f2.x; acc[5] += w * f2.y;
            acc[6] += w * f3.x; acc[7] += w * f3.y;
        }
#pragma unroll
        for (int u = 0; u < 4; u++) { cs[u] = ns[u]; cw[u] = nw[u]; }
    }
    float inv = 1.f / wsum;
    const float4* bp = (const float4*)(bias + col0);
    float4 b0 = bp[0], b1 = bp[1];
    h2x4 pack;
    pack.a = __floats2half2_rn(fmaxf(acc[0]*inv + b0.x, 0.f), fmaxf(acc[1]*inv + b0.y, 0.f));
    pack.b = __floats2half2_rn(fmaxf(acc[2]*inv + b0.z, 0.f), fmaxf(acc[3]*inv + b0.w, 0.f));
    pack.c = __floats2half2_rn(fmaxf(acc[4]*inv + b1.x, 0.f), fmaxf(acc[5]*inv + b1.y, 0.f));
    pack.d = __floats2half2_rn(fmaxf(acc[6]*inv + b1.z, 0.f), fmaxf(acc[7]*inv + b1.w, 0.f));
    *(h2x4*)(out + (size_t)node * D1 + col0) = pack;
}

// ---------------- GAT layer 2 fused with ReLU + global_add_pool ----------------
__global__ __launch_bounds__(256) void gat2_k(
    const __half* __restrict__ feat, const float* __restrict__ w2,
    const float* __restrict__ bias, const int* __restrict__ batch, int N)
{
    int warp = threadIdx.x >> 5, lane = threadIdx.x & 31;
    int node = blockIdx.x * 8 + warp;
    if (node >= N) return;
    int beg = g_off[node], end = g_off[node + 1];

    float2 acc = make_float2(0.f, 0.f);
    float wsum = 0.f;
    const __half* fb = feat + lane * 2;

    int cs[4]; float cw[4];
#pragma unroll
    for (int u = 0; u < 4; u++) {
        int e = beg + u; bool ok = e < end; e = ok ? e : end - 1;
        cs[u] = g_csr[e];
        cw[u] = ok ? w2[e] : 0.f;
    }
    for (int i = beg; i < end; i += 4) {
        int ns[4] = {0,0,0,0}; float nw[4] = {0,0,0,0};
        int nb = i + 4;
        if (nb < end) {
#pragma unroll
            for (int u = 0; u < 4; u++) {
                int e = nb + u; bool ok = e < end; e = ok ? e : end - 1;
                ns[u] = g_csr[e];
                nw[u] = ok ? w2[e] : 0.f;
            }
        }
#pragma unroll
        for (int u = 0; u < 4; u++) {
            float w = cw[u];
            wsum += w;
            __half2 h = *(const __half2*)(fb + (size_t)cs[u] * HID);
            float2 f = __half22float2(h);
            acc.x += w * f.x;
            acc.y += w * f.y;
        }
#pragma unroll
        for (int u = 0; u < 4; u++) { cs[u] = ns[u]; cw[u] = nw[u]; }
    }
    float inv = 1.f / wsum;
    int col = lane * 2;
    float v0 = fmaxf(acc.x * inv + bias[col],     0.f);
    float v1 = fmaxf(acc.y * inv + bias[col + 1], 0.f);
    int g = batch[node];
    atomicAdd(&g_pool[g * HID + col],     v0);
    atomicAdd(&g_pool[g * HID + col + 1], v1);
}

// ---------------- FC ----------------
__global__ void fc_k(const float* __restrict__ W, const float* __restrict__ b,
                     float* __restrict__ out)
{
    int t = threadIdx.x;
    if (t >= N_GRAPHS * 10) return;
    int g = t / 10, o = t % 10;
    float s = b[o];
#pragma unroll
    for (int c = 0; c < HID; c++) s += g_pool[g * HID + c] * W[c * 10 + o];
    out[t] = s;
}

// ---------------- host ----------------
extern "C" void kernel_launch(void* const* d_in, const int* in_sizes, int n_in,
                              void* d_out, int out_size)
{
    const float* x      = (const float*)d_in[0];
    const int*   ei     = (const int*)  d_in[1];
    const int*   batch  = (const int*)  d_in[2];
    const float* W1     = (const float*)d_in[3];
    const float* a_src1 = (const float*)d_in[4];
    const float* a_dst1 = (const float*)d_in[5];
    const float* b1     = (const float*)d_in[6];
    const float* W2     = (const float*)d_in[7];
    const float* a_src2 = (const float*)d_in[8];
    const float* a_dst2 = (const float*)d_in[9];
    const float* b2     = (const float*)d_in[10];
    const float* W_fc   = (const float*)d_in[11];
    const float* b_fc   = (const float*)d_in[12];

    int N = in_sizes[0] / IN_DIM;      // 50000
    int E = in_sizes[1] / 2;           // 800000
    int ET = E + N;

    __half *h1, *o1, *h2;
    float *as1, *ad1, *as2, *ad2, *w1b, *w2b;
    cudaGetSymbolAddress((void**)&h1,  g_h1);
    cudaGetSymbolAddress((void**)&o1,  g_o1);
    cudaGetSymbolAddress((void**)&h2,  g_h2);
    cudaGetSymbolAddress((void**)&as1, g_as1);
    cudaGetSymbolAddress((void**)&ad1, g_ad1);
    cudaGetSymbolAddress((void**)&as2, g_as2);
    cudaGetSymbolAddress((void**)&ad2, g_ad2);
    cudaGetSymbolAddress((void**)&w1b, g_w1);
    cudaGetSymbolAddress((void**)&w2b, g_w2);

    // 1..3: zero + degree histogram + offsets
    zero_k<<<(N * H1 + 255) / 256, 256>>>(N);
    hist_k<<<(E + 255) / 256, 256>>>(ei, E);
    scan_k<<<1, 1024>>>(N);
    // 4: fp16 GEMM1 + alpha epilogue (profiled slot)
    mma_ep<128, H1><<<dim3((N + 127) / 128, D1 / 128), 256>>>(
        x, W1, h1, a_src1, a_dst1, as1, ad1, N, D1, IN_DIM);
    // 5: CSR scatter (+dst) + self-loops
    scatter_self_k<<<(E + N + 255) / 256, 256>>>(ei, E, N);
    // 6: edge weights layer 1
    wk1_k<<<(ET * H1 + 255) / 256, 256>>>(ET);
    // 7: GAT layer 1 aggregation
    gat1_k<<<(N + 3) / 4, 256>>>(h1, w1b, b1, o1, N);
    // 8: fp16 GEMM2 + alpha epilogue (A fp16)
    mma_ep<64, 1><<<dim3((N + 127) / 128, 1), 256>>>(
        o1, W2, h2, a_src2, a_dst2, as2, ad2, N, HID, D1);
    // 9: edge weights layer 2
    wk2_k<<<(ET + 255) / 256, 256>>>(ET);
    // 10: GAT layer 2 fused with ReLU + pool
    gat2_k<<<(N + 7) / 8, 256>>>(h2, w2b, b2, batch, N);
    // 11: FC
    fc_k<<<1, 640>>>(W_fc, b_fc, (float*)d_out);
}